// round 1
// baseline (speedup 1.0000x reference)
#include <cuda_runtime.h>

// BoxBlur 13x13, reflect padding, depthwise over (B=8, C=64, H=512, W=512) fp32.
// Separable: horizontal 13-sum -> vertical 13-sum -> * kernel[0] (uniform box).

#define B_  8
#define C_  64
#define H_  512
#define W_  512
#define K_  13
#define R_  6            // (K-1)/2, symmetric since K odd
#define TX  128          // output tile width per CTA
#define TY  32           // output tile height per CTA
#define RAW_W (TX + 2 * R_)   // 140
#define RAW_H (TY + 2 * R_)   // 44
#define NTHREADS 256

__device__ __forceinline__ int reflect_idx(int i, int n) {
    // jnp.pad mode="reflect": -1 -> 1, n -> n-2. Pad (6) < n (512): single fold.
    if (i < 0) i = -i;
    if (i >= n) i = 2 * n - 2 - i;
    return i;
}

__global__ __launch_bounds__(NTHREADS)
void boxblur_kernel(const float* __restrict__ in,
                    const float* __restrict__ kern,
                    float* __restrict__ out) {
    __shared__ float raw[RAW_H][RAW_W];   // 44*140*4 = 24640 B
    __shared__ float hb[RAW_H][TX];       // 44*128*4 = 22528 B

    const int plane = blockIdx.z;                   // b*C + c
    const float* __restrict__ ip = in  + (size_t)plane * (H_ * W_);
    float* __restrict__ op       = out + (size_t)plane * (H_ * W_);

    const int x0 = blockIdx.x * TX;
    const int y0 = blockIdx.y * TY;
    const int tid = threadIdx.x;
    const float k0 = kern[0];   // uniform box weight

    // ---- Load halo tile with reflect indexing ----
    #pragma unroll 4
    for (int i = tid; i < RAW_H * RAW_W; i += NTHREADS) {
        const int ry = i / RAW_W;
        const int rx = i - ry * RAW_W;
        const int gy = reflect_idx(y0 + ry - R_, H_);
        const int gx = reflect_idx(x0 + rx - R_, W_);
        raw[ry][rx] = ip[gy * W_ + gx];
    }
    __syncthreads();

    // ---- Horizontal 13-tap sums (full vertical extent incl. halo rows) ----
    #pragma unroll 4
    for (int i = tid; i < RAW_H * TX; i += NTHREADS) {
        const int ry = i >> 7;          // i / 128
        const int rx = i & (TX - 1);    // i % 128
        float s = 0.0f;
        #pragma unroll
        for (int t = 0; t < K_; t++) s += raw[ry][rx + t];
        hb[ry][rx] = s;
    }
    __syncthreads();

    // ---- Vertical 13-tap sums, scale, store ----
    #pragma unroll 4
    for (int i = tid; i < TY * TX; i += NTHREADS) {
        const int ry = i >> 7;
        const int rx = i & (TX - 1);
        float s = 0.0f;
        #pragma unroll
        for (int t = 0; t < K_; t++) s += hb[ry + t][rx];
        op[(y0 + ry) * W_ + (x0 + rx)] = s * k0;
    }
}

extern "C" void kernel_launch(void* const* d_in, const int* in_sizes, int n_in,
                              void* d_out, int out_size) {
    const float* input  = (const float*)d_in[0];   // (8, 64, 512, 512) fp32
    const float* kernel = (const float*)d_in[1];   // (1, 13, 13) fp32, uniform
    float* out = (float*)d_out;

    dim3 grid(W_ / TX, H_ / TY, B_ * C_);  // (4, 16, 512)
    boxblur_kernel<<<grid, NTHREADS>>>(input, kernel, out);
}

// round 2
// speedup vs baseline: 2.8476x; 2.8476x over previous
#include <cuda_runtime.h>

// BoxBlur 13x13 reflect, (8,64,512,512) fp32. Separable sliding-window version.
// CTA = one 32-row x full-width (512) stripe of one plane.
//  Pass 1: vertical 13-sums, gmem -> smem, thread-per-column, register ring.
//  Pass 2: horizontal 13-sums, smem sliding window (lanes on rows, no conflicts),
//          staged to smem, then coalesced store.

#define Wd 512
#define Hd 512
#define TY 32
#define NT 512
#define PW 513          // odd stride -> conflict-free column access
#define KHALF 6
#define RAWH (TY + 12)  // 44 input rows per stripe

#define SMEM_BYTES ((TY * PW + 16 * PW) * 4)   // vs + os = 98496 B

__device__ __forceinline__ int reflect_i(int i, int n) {
    // jnp.pad 'reflect', pad (6) < n: single fold.
    if (i < 0) i = -i;
    if (i >= n) i = 2 * n - 2 - i;
    return i;
}

__global__ __launch_bounds__(NT, 2)
void boxblur2(const float* __restrict__ in,
              const float* __restrict__ kern,
              float* __restrict__ out) {
    extern __shared__ float sm[];
    float* __restrict__ vs = sm;            // [TY][PW]  vertical sums
    float* __restrict__ os = sm + TY * PW;  // [16][PW]  output staging (half tile)

    const int ytile = blockIdx.x;
    const int plane = blockIdx.y;
    const int y0 = ytile * TY;
    const float* __restrict__ ip = in  + (size_t)plane * (Hd * Wd);
    float*       __restrict__ op = out + (size_t)plane * (Hd * Wd);
    const int t = threadIdx.x;              // 0..511
    const float k0 = kern[0];               // 1/169, applied once

    // ---------------- Pass 1: vertical running sums, thread t = column t ----
    {
        float ring[13];
        float s = 0.0f;
        #pragma unroll
        for (int j = 0; j < RAWH; j++) {
            const int gy = reflect_i(y0 + j - KHALF, Hd);
            const float v = ip[gy * Wd + t];        // coalesced: warp = 128B row chunk
            s += v;
            if (j >= 12) {
                vs[(j - 12) * PW + t] = s;          // conflict-free (consecutive t)
                s -= ring[(j - 12) % 13];
            }
            ring[j % 13] = v;
        }
    }
    __syncthreads();

    // ---------------- Pass 2: horizontal sliding sums in two 16-row halves --
    const int rl  = t & 15;        // local row within half
    const int seg = t >> 4;        // 0..31, 16-wide x segment
    const int xb  = seg * 16;

    #pragma unroll
    for (int h = 0; h < 2; h++) {
        const int row = h * 16 + rl;
        float ring[13];
        float s = 0.0f;
        // init window around xb (reflect only matters for seg 0 / seg 31)
        #pragma unroll
        for (int k = 0; k < 13; k++) {
            const int x = reflect_i(xb - KHALF + k, Wd);
            const float v = vs[row * PW + x];       // lanes differ by row*513 -> no conflicts
            ring[k] = v;
            s += v;
        }
        #pragma unroll
        for (int i = 0; i < 16; i++) {
            os[rl * PW + xb + i] = s * k0;
            const int xn = reflect_i(xb + i + KHALF + 1, Wd);
            const float v = vs[row * PW + xn];
            s += v - ring[i % 13];
            ring[i % 13] = v;
        }
        __syncthreads();
        // flush half tile: coalesced (lanes along x)
        #pragma unroll
        for (int r = 0; r < 16; r++) {
            op[(size_t)(y0 + h * 16 + r) * Wd + t] = os[r * PW + t];
        }
        __syncthreads();
    }
}

extern "C" void kernel_launch(void* const* d_in, const int* in_sizes, int n_in,
                              void* d_out, int out_size) {
    const float* input  = (const float*)d_in[0];   // (8,64,512,512) fp32
    const float* kernel = (const float*)d_in[1];   // (1,13,13) fp32 uniform
    float* out = (float*)d_out;

    cudaFuncSetAttribute(boxblur2, cudaFuncAttributeMaxDynamicSharedMemorySize,
                         SMEM_BYTES);

    dim3 grid(Hd / TY, 8 * 64);   // (16 y-tiles, 512 planes)
    boxblur2<<<grid, NT, SMEM_BYTES>>>(input, kernel, out);
}

// round 3
// speedup vs baseline: 2.9191x; 1.0251x over previous
#include <cuda_runtime.h>

// BoxBlur 13x13 reflect, (8,64,512,512) fp32. Separable, sliding-window.
// CTA = 16-row x 512-wide stripe. 3 CTAs/SM target (smem 49.3KB, regs<=41).
// Pass 1: vertical running sum, re-load outgoing row (L1/L2 hit) instead of
//         a 13-deep register ring -> low reg pressure.
// Pass 2: horizontal sliding sums (8-row halves), staged to os, float4 flush.

#define Wd 512
#define Hd 512
#define TY 16
#define NT 512
#define PW 513            // vs stride (odd -> conflict-free row-strided access)
#define OW 516            // os stride (mult of 4 -> aligned float4, still conflict-free)
#define KHALF 6

#define SMEM_FLOATS (TY * PW + 8 * OW)
#define SMEM_BYTES  (SMEM_FLOATS * 4)       // 49344 B

__device__ __forceinline__ int reflect_i(int i, int n) {
    // jnp.pad 'reflect', pad (6) < n: single fold.
    if (i < 0) i = -i;
    if (i >= n) i = 2 * n - 2 - i;
    return i;
}

__global__ __launch_bounds__(NT, 3)
void boxblur3(const float* __restrict__ in,
              const float* __restrict__ kern,
              float* __restrict__ out) {
    extern __shared__ float sm[];
    float* __restrict__ vs = sm;             // [TY][PW]  vertical 13-sums
    float* __restrict__ os = sm + TY * PW;   // [8][OW]   output staging

    const int ytile = blockIdx.x;
    const int plane = blockIdx.y;
    const int y0 = ytile * TY;
    const float* __restrict__ ip = in  + (size_t)plane * (Hd * Wd);
    float*       __restrict__ op = out + (size_t)plane * (Hd * Wd);
    const int t = threadIdx.x;               // 0..511
    const float k0 = kern[0];                // 1/169

    // ---- Pass 1: vertical running 13-sum, thread t = column t ----
    {
        float s = 0.0f;
        #pragma unroll
        for (int j = -KHALF; j < KHALF; j++)           // 12 init rows
            s += ip[reflect_i(y0 + j, Hd) * Wd + t];
        #pragma unroll
        for (int j = 0; j < TY; j++) {
            s += ip[reflect_i(y0 + j + KHALF, Hd) * Wd + t];   // incoming row
            vs[j * PW + t] = s;
            s -= ip[reflect_i(y0 + j - KHALF, Hd) * Wd + t];   // outgoing (L1/L2 hit)
        }
    }
    __syncthreads();

    // ---- Pass 2: horizontal sliding 13-sums, two 8-row halves ----
    const int rl  = t & 7;          // local row within half
    const int seg = t >> 3;         // 0..63, 8-wide x segment
    const int xb  = seg * 8;
    const int g   = t & 127;        // flush: float4 group
    const int r2  = t >> 7;         // flush: row base (0..3)

    #pragma unroll
    for (int h = 0; h < 2; h++) {
        const int row = h * 8 + rl;
        const float* __restrict__ vrow = vs + row * PW;
        float ring[13];
        float s = 0.0f;
        #pragma unroll
        for (int k = 0; k < 13; k++) {
            const float v = vrow[reflect_i(xb - KHALF + k, Wd)];
            ring[k] = v;
            s += v;
        }
        #pragma unroll
        for (int i = 0; i < 8; i++) {
            os[rl * OW + xb + i] = s * k0;
            const float v = vrow[reflect_i(xb + i + KHALF + 1, Wd)];
            s += v - ring[i];
            ring[i] = v;
        }
        __syncthreads();
        // flush 8 rows with float4 (coalesced STG.128)
        #pragma unroll
        for (int rr = 0; rr < 2; rr++) {
            const int rowf = r2 + rr * 4;
            const float4 v4 = *(const float4*)&os[rowf * OW + 4 * g];
            *(float4*)&op[(size_t)(y0 + h * 8 + rowf) * Wd + 4 * g] = v4;
        }
        __syncthreads();
    }
}

extern "C" void kernel_launch(void* const* d_in, const int* in_sizes, int n_in,
                              void* d_out, int out_size) {
    const float* input  = (const float*)d_in[0];   // (8,64,512,512) fp32
    const float* kernel = (const float*)d_in[1];   // (1,13,13) fp32 uniform
    float* out = (float*)d_out;

    cudaFuncSetAttribute(boxblur3, cudaFuncAttributeMaxDynamicSharedMemorySize,
                         SMEM_BYTES);

    dim3 grid(Hd / TY, 8 * 64);    // (32 y-tiles, 512 planes)
    boxblur3<<<grid, NT, SMEM_BYTES>>>(input, kernel, out);
}